// round 6
// baseline (speedup 1.0000x reference)
#include <cuda_runtime.h>
#include <cuda_bf16.h>
#include <math.h>

#define Bv 32
#define Sv 128
#define Dv 300
#define VOC 20000
#define Kv 8
#define RROWS 4096
#define G4 1200
#define ESTRIDE 20004
#define NC_LSTM 75
#define SPLITK 5
#define KSPL2 2000
#define VPART_LD 304

// ---------------- scratch (static device globals; zero-initialized) ----------
__device__ float g_E[(size_t)RROWS * ESTRIDE];
__device__ unsigned g_rowmax[RROWS];
__device__ float g_rowsum[RROWS];
__device__ float g_pl[RROWS];
__device__ float g_V[RROWS * Dv];
__device__ float g_Vpart[(size_t)SPLITK * RROWS * VPART_LD];
__device__ float g_XIT[(size_t)Sv * G4 * Bv];
__device__ float g_hT[2][Dv * Bv];
__device__ float g_H[Bv * Kv * Dv];
__device__ unsigned g_bar;

__device__ unsigned g_wordsH[RROWS * 160], g_wordsL[RROWS * 160];
__device__ unsigned g_WH[160 * 304], g_WL[160 * 304];
__device__ unsigned g_XH[RROWS * 160], g_XL[RROWS * 160];
__device__ unsigned g_CTH[(size_t)160 * ESTRIDE], g_CTL[(size_t)160 * ESTRIDE];
__device__ unsigned g_EH[(size_t)RROWS * 10000], g_EL[(size_t)RROWS * 10000];
__device__ unsigned g_vocH[10000 * 304], g_vocL[10000 * 304];
__device__ unsigned g_VH[RROWS * 160], g_VL[RROWS * 160];
__device__ unsigned g_WihTH[160 * 1204], g_WihTL[160 * 1204];

__device__ __forceinline__ float sigmoidf_(float x) {
    return 1.0f / (1.0f + __expf(-x));
}

// order-preserving float<->uint for atomicMax
__device__ __forceinline__ unsigned fenc(float f) {
    unsigned b = __float_as_uint(f);
    return (b & 0x80000000u) ? ~b : (b | 0x80000000u);
}
__device__ __forceinline__ float fdec(unsigned u) {
    return __uint_as_float((u & 0x80000000u) ? (u ^ 0x80000000u) : ~u);
}

__device__ __forceinline__ void split2(float x0, float x1, unsigned& hi,
                                       unsigned& lo) {
    __nv_bfloat16 h0 = __float2bfloat16_rn(x0);
    __nv_bfloat16 h1 = __float2bfloat16_rn(x1);
    float r0 = x0 - __bfloat162float(h0);
    float r1 = x1 - __bfloat162float(h1);
    __nv_bfloat16 l0 = __float2bfloat16_rn(r0);
    __nv_bfloat16 l1 = __float2bfloat16_rn(r1);
    hi = ((unsigned)__bfloat16_as_ushort(h1) << 16) | __bfloat16_as_ushort(h0);
    lo = ((unsigned)__bfloat16_as_ushort(l1) << 16) | __bfloat16_as_ushort(l0);
}

__device__ __forceinline__ void mma16(float* c, const unsigned* a,
                                      const unsigned* b) {
    asm volatile(
        "mma.sync.aligned.m16n8k16.row.col.f32.bf16.bf16.f32 "
        "{%0,%1,%2,%3}, {%4,%5,%6,%7}, {%8,%9}, {%0,%1,%2,%3};\n"
        : "+f"(c[0]), "+f"(c[1]), "+f"(c[2]), "+f"(c[3])
        : "r"(a[0]), "r"(a[1]), "r"(a[2]), "r"(a[3]), "r"(b[0]), "r"(b[1]));
}

__device__ __forceinline__ void ldsm4(unsigned* r, unsigned addr) {
    asm volatile(
        "ldmatrix.sync.aligned.m8n8.x4.shared.b16 {%0,%1,%2,%3}, [%4];"
        : "=r"(r[0]), "=r"(r[1]), "=r"(r[2]), "=r"(r[3])
        : "r"(addr));
}

__device__ __forceinline__ void cpa16(unsigned* dst, const unsigned* src,
                                      int bytes) {
    unsigned d = (unsigned)__cvta_generic_to_shared(dst);
    asm volatile("cp.async.cg.shared.global [%0], [%1], 16, %2;\n" ::"r"(d),
                 "l"(src), "r"(bytes));
}
__device__ __forceinline__ void cpa_commit() {
    asm volatile("cp.async.commit_group;\n");
}
__device__ __forceinline__ void cpa_wait2() {
    asm volatile("cp.async.wait_group 2;\n");
}

// ---------------- prepasses ---------------------------------------------------
__global__ void k_splitA(const float* __restrict__ src, int M, int K,
                         unsigned* __restrict__ hi, unsigned* __restrict__ lo,
                         int lda2) {
    int idx = blockIdx.x * 256 + threadIdx.x;
    int K2 = K >> 1;
    if (idx >= M * K2) return;
    int m = idx / K2, j = idx - m * K2;
    float2 v = *(const float2*)&src[(size_t)m * K + 2 * j];
    unsigned h, l;
    split2(v.x, v.y, h, l);
    hi[(size_t)m * lda2 + j] = h;
    lo[(size_t)m * lda2 + j] = l;
}

__global__ void k_splitB_N(const float* __restrict__ src, int K, int N,
                           unsigned* __restrict__ hi, unsigned* __restrict__ lo,
                           int ldo) {
    int idx = blockIdx.x * 256 + threadIdx.x;
    int K2 = K >> 1;
    if (idx >= K2 * N) return;
    int k2 = idx / N, n = idx - k2 * N;
    float a = src[(size_t)(2 * k2) * N + n];
    float b = src[(size_t)(2 * k2 + 1) * N + n];
    unsigned h, l;
    split2(a, b, h, l);
    hi[(size_t)k2 * ldo + n] = h;
    lo[(size_t)k2 * ldo + n] = l;
}

__global__ void k_splitB_T(const float* __restrict__ src, int Nsrc, int K,
                           const float* __restrict__ alt,
                           unsigned* __restrict__ hi, unsigned* __restrict__ lo,
                           int ldo) {
    __shared__ float tile[32][33];
    int n0 = blockIdx.x * 32, k0 = blockIdx.y * 32;
    int x = threadIdx.x, y = threadIdx.y;
    int Ntot = Nsrc + (alt ? 1 : 0);
    for (int i = y; i < 32; i += 8) {
        int n = n0 + i, k = k0 + x;
        float v = 0.f;
        if (k < K) {
            if (n < Nsrc) v = src[(size_t)n * K + k];
            else if (alt != nullptr && n == Nsrc) v = alt[k];
        }
        tile[i][x] = v;
    }
    __syncthreads();
    for (int i = y; i < 16; i += 8) {
        int k2 = (k0 >> 1) + i;
        int n = n0 + x;
        if (n < Ntot) {
            unsigned h, l;
            split2(tile[x][2 * i], tile[x][2 * i + 1], h, l);
            hi[(size_t)k2 * ldo + n] = h;
            lo[(size_t)k2 * ldo + n] = l;
        }
    }
}

// ---------------- split-bf16 NN GEMM, cp.async 4-stage, ldmatrix A -----------
// BM=128, BN=128, BK=32 (16 k-pairs), 512 threads, 16 warps (4m x 4n).
// epi 0: fp32 C (+bias). epi 2: fp32 partial. epi 3: split packs.
// epi 4: bias + XIT scatter. epi 5: fp32 C + fused row-max atomics.
#define APITCH 20
#define ABUFW 2560
#define BPITCH 132
#define BBUFW 2112
#define STGW 9344
#define NSTAGE 4
#define MMA_SMEM (NSTAGE * STGW * 4)

__global__ __launch_bounds__(512) void mma_nn(
    const unsigned* __restrict__ Agh, const unsigned* __restrict__ Agl, int lda2,
    const unsigned* __restrict__ Bgh, const unsigned* __restrict__ Bgl, int ldb,
    const float* __restrict__ bias, float* __restrict__ C, int ldc,
    unsigned* __restrict__ Ch, unsigned* __restrict__ Cl, int ldc2,
    int N, int ksplit2, int K2, size_t partStride, int epi) {
    extern __shared__ unsigned smem[];
    int tid = threadIdx.x;
    int m0 = blockIdx.x * 128, n0 = blockIdx.y * 128;
    int kb2 = blockIdx.z * ksplit2;
    int ks2 = K2 - kb2;
    if (ks2 > ksplit2) ks2 = ksplit2;
    int nIter = (ks2 + 15) >> 4;

    int lane = tid & 31, w = tid >> 5;
    int wm = (w >> 2) * 32, wn = (w & 3) * 32;

    int am = tid >> 2, ac = tid & 3;
    int bk = tid >> 5, bc = tid & 31;
    int c0b = n0 + bc * 4;
    int validb = N - c0b;
    int bbytes = validb >= 4 ? 16 : (validb > 0 ? validb * 4 : 0);
    int ccb = (bbytes > 0) ? c0b : 0;

    // ldmatrix per-lane byte offset within A buffer (stage-relative)
    unsigned smem_u32 = (unsigned)__cvta_generic_to_shared(smem);
    int arow = wm + ((lane >> 3) & 1) * 8 + (lane & 7);
    unsigned aoff = (unsigned)(arow * 80 + ((lane >> 4) * 16));

    float c[2][4][4];
#pragma unroll
    for (int i = 0; i < 2; i++)
#pragma unroll
        for (int j = 0; j < 4; j++)
#pragma unroll
            for (int q = 0; q < 4; q++) c[i][j][q] = 0.f;

    // prologue: issue stages 0..2
#pragma unroll
    for (int p = 0; p < NSTAGE - 1; p++) {
        if (p < nIter) {
            unsigned* sb = smem + p * STGW;
            size_t aidx = (size_t)(m0 + am) * lda2 + kb2 + (p << 4) + ac * 4;
            cpa16(&sb[am * APITCH + ac * 4], Agh + aidx, 16);
            cpa16(&sb[ABUFW + am * APITCH + ac * 4], Agl + aidx, 16);
            size_t bidx = (size_t)(kb2 + (p << 4) + bk) * ldb + ccb;
            cpa16(&sb[2 * ABUFW + bk * BPITCH + bc * 4], Bgh + bidx, bbytes);
            cpa16(&sb[2 * ABUFW + BBUFW + bk * BPITCH + bc * 4], Bgl + bidx,
                  bbytes);
        }
        cpa_commit();
    }

    for (int it = 0; it < nIter; ++it) {
        cpa_wait2();
        __syncthreads();

        // issue stage it+3 (overwrites buffer of it-1; all consumers synced)
        if (it + NSTAGE - 1 < nIter) {
            unsigned* sb2 = smem + ((it + NSTAGE - 1) % NSTAGE) * STGW;
            int k2base = (it + NSTAGE - 1) << 4;
            size_t aidx = (size_t)(m0 + am) * lda2 + kb2 + k2base + ac * 4;
            cpa16(&sb2[am * APITCH + ac * 4], Agh + aidx, 16);
            cpa16(&sb2[ABUFW + am * APITCH + ac * 4], Agl + aidx, 16);
            size_t bidx = (size_t)(kb2 + k2base + bk) * ldb + ccb;
            cpa16(&sb2[2 * ABUFW + bk * BPITCH + bc * 4], Bgh + bidx, bbytes);
            cpa16(&sb2[2 * ABUFW + BBUFW + bk * BPITCH + bc * 4], Bgl + bidx,
                  bbytes);
        }
        cpa_commit();

        int buf = it % NSTAGE;
        unsigned stage_u32 = smem_u32 + buf * (STGW * 4);
        const unsigned* sb = smem + buf * STGW;
        const unsigned* BhiB = sb + 2 * ABUFW;
        const unsigned* BloB = sb + 2 * ABUFW + BBUFW;

#pragma unroll
        for (int s = 0; s < 2; s++) {
            int k2a = s * 8 + (lane & 3);
            unsigned ah[2][4], al[2][4];
#pragma unroll
            for (int mi = 0; mi < 2; mi++) {
                unsigned a_hi = stage_u32 + aoff + (unsigned)(mi * 16 * 80 + s * 32);
                ldsm4(ah[mi], a_hi);
                ldsm4(al[mi], a_hi + ABUFW * 4);
            }
#pragma unroll
            for (int nj = 0; nj < 4; nj++) {
                int nb = wn + nj * 8 + (lane >> 2);
                unsigned bh[2], bl[2];
                bh[0] = BhiB[k2a * BPITCH + nb];
                bh[1] = BhiB[(k2a + 4) * BPITCH + nb];
                bl[0] = BloB[k2a * BPITCH + nb];
                bl[1] = BloB[(k2a + 4) * BPITCH + nb];
#pragma unroll
                for (int mi = 0; mi < 2; mi++) {
                    mma16(c[mi][nj], ah[mi], bh);
                    mma16(c[mi][nj], ah[mi], bl);
                    mma16(c[mi][nj], al[mi], bh);
                }
            }
        }
    }

    // ---- epilogue ----
#pragma unroll
    for (int mi = 0; mi < 2; mi++) {
        int r1 = m0 + wm + mi * 16 + (lane >> 2);
        int r2 = r1 + 8;
#pragma unroll
        for (int nj = 0; nj < 4; nj++) {
            int col0 = n0 + wn + nj * 8 + (lane & 3) * 2;
            if (epi == 3) {
                if (col0 + 1 < N) {
                    unsigned h, l;
                    split2(c[mi][nj][0], c[mi][nj][1], h, l);
                    Ch[(size_t)r1 * ldc2 + (col0 >> 1)] = h;
                    Cl[(size_t)r1 * ldc2 + (col0 >> 1)] = l;
                    split2(c[mi][nj][2], c[mi][nj][3], h, l);
                    Ch[(size_t)r2 * ldc2 + (col0 >> 1)] = h;
                    Cl[(size_t)r2 * ldc2 + (col0 >> 1)] = l;
                }
            } else if (epi == 4) {
#pragma unroll
                for (int q = 0; q < 2; q++) {
                    int col = col0 + q;
                    if (col < N) {
                        float b = bias[col];
                        C[((size_t)(r1 & 127) * G4 + col) * 32 + (r1 >> 7)] =
                            c[mi][nj][q] + b;
                        C[((size_t)(r2 & 127) * G4 + col) * 32 + (r2 >> 7)] =
                            c[mi][nj][2 + q] + b;
                    }
                }
            } else {
                float* Cp = C + blockIdx.z * partStride;
#pragma unroll
                for (int q = 0; q < 2; q++) {
                    int col = col0 + q;
                    if (col < N) {
                        float v1 = c[mi][nj][q];
                        float v2 = c[mi][nj][2 + q];
                        if (epi == 0 && bias != nullptr) {
                            v1 += bias[col];
                            v2 += bias[col];
                        }
                        Cp[(size_t)r1 * ldc + col] = v1;
                        Cp[(size_t)r2 * ldc + col] = v2;
                    }
                }
            }
        }
    }

    if (epi == 5) {
        // fused row-max: per thread, per mi: rows r1, r2 over its 8 valid cols
#pragma unroll
        for (int mi = 0; mi < 2; mi++) {
            int r1 = m0 + wm + mi * 16 + (lane >> 2);
            float m1 = -1e30f, m2 = -1e30f;
#pragma unroll
            for (int nj = 0; nj < 4; nj++) {
                int col0 = n0 + wn + nj * 8 + (lane & 3) * 2;
#pragma unroll
                for (int q = 0; q < 2; q++) {
                    if (col0 + q < N) {
                        m1 = fmaxf(m1, c[mi][nj][q]);
                        m2 = fmaxf(m2, c[mi][nj][2 + q]);
                    }
                }
            }
            // reduce across the 4 lanes sharing these rows (lane^1, lane^2)
#pragma unroll
            for (int off = 1; off <= 2; off <<= 1) {
                m1 = fmaxf(m1, __shfl_xor_sync(0xffffffffu, m1, off));
                m2 = fmaxf(m2, __shfl_xor_sync(0xffffffffu, m2, off));
            }
            if ((lane & 3) == 0) {
                atomicMax(&g_rowmax[r1], fenc(m1));
                atomicMax(&g_rowmax[r1 + 8], fenc(m2));
            }
        }
    }
}

// ---------------- single-pass softmax (row max precomputed) ------------------
__global__ void k_softmax(const float* __restrict__ E, unsigned* __restrict__ EH,
                          unsigned* __restrict__ EL, float* __restrict__ pl,
                          float* __restrict__ rowsum) {
    int r = blockIdx.x;
    const float2* row2 = (const float2*)(E + (size_t)r * ESTRIDE);
    int tid = threadIdx.x;  // 256
    __shared__ float red[256];
    float m = fdec(g_rowmax[r]);
    float sum = 0.f;
    for (int j = tid; j < 10000; j += 256) {
        float2 f = row2[j];
        float e0 = __expf(f.x - m);
        float e1 = __expf(f.y - m);
        sum += e0 + e1;
        unsigned h, l;
        split2(e0, e1, h, l);
        EH[(size_t)r * 10000 + j] = h;
        EL[(size_t)r * 10000 + j] = l;
    }
    if (tid == 0) {
        float e = __expf(E[(size_t)r * ESTRIDE + VOC] - m);
        pl[r] = e;
        sum += e;
    }
    red[tid] = sum;
    __syncthreads();
    for (int s = 128; s > 0; s >>= 1) {
        if (tid < s) red[tid] += red[tid + s];
        __syncthreads();
    }
    if (tid == 0) rowsum[r] = red[0];
}

// ---------------- split-K reduce + V epilogue + V split ----------------------
__global__ void k_vreduce(const float* __restrict__ part,
                          const float* __restrict__ pl,
                          const float* __restrict__ rowsum,
                          const float* __restrict__ words,
                          float* __restrict__ V, unsigned* __restrict__ VH,
                          unsigned* __restrict__ VL) {
    int idx = blockIdx.x * 256 + threadIdx.x;
    if (idx >= RROWS * 150) return;
    int r = idx / 150, j = idx - r * 150;
    int d0 = 2 * j;
    float s0 = 0.f, s1 = 0.f;
#pragma unroll
    for (int z = 0; z < SPLITK; z++) {
        const float* p = part + (size_t)z * RROWS * VPART_LD +
                         (size_t)r * VPART_LD + d0;
        s0 += p[0];
        s1 += p[1];
    }
    float p_l = pl[r];
    float inv = 1.0f / rowsum[r];
    float v0 = (s0 + p_l * words[(size_t)r * Dv + d0]) * inv;
    float v1 = (s1 + p_l * words[(size_t)r * Dv + d0 + 1]) * inv;
    V[(size_t)r * Dv + d0] = v0;
    V[(size_t)r * Dv + d0 + 1] = v1;
    unsigned h, l;
    split2(v0, v1, h, l);
    VH[(size_t)r * 160 + j] = h;
    VL[(size_t)r * 160 + j] = l;
}

// ---------------- inits -------------------------------------------------------
__global__ void k_init0() {
    int i = blockIdx.x * blockDim.x + threadIdx.x;
    if (i < RROWS) g_rowmax[i] = 0u;
}
__global__ void k_init() {
    int i = blockIdx.x * blockDim.x + threadIdx.x;
    if (i < Dv * Bv) g_hT[0][i] = 0.f;
    if (i == 0) g_bar = 0u;
}

// ---------------- persistent LSTM (lane = batch) ------------------------------
__global__ __launch_bounds__(256) void k_lstm(const float* __restrict__ XIT,
                                              const float* __restrict__ Whh,
                                              const float* __restrict__ bhh,
                                              const int* __restrict__ lengths) {
    extern __shared__ float sm[];
    float* Wsh = sm;              // [16][300]
    float* hTs = Wsh + 4800;      // [300][32]
    float* psum = hTs + 9600;     // [2][16][32]
    float* bsh = psum + 1024;     // [16]
    int* lsh = (int*)(bsh + 16);  // [32]

    int tid = threadIdx.x, lane = tid & 31, w = tid >> 5;
    int d0 = blockIdx.x * 4;
    int half = w >> 2;
    int rg = (w & 3) * 4;

    for (int i = tid; i < 4800; i += 256) {
        int row = i / 300, d = i - row * 300;
        int g = row >> 2, j = row & 3;
        Wsh[i] = Whh[(size_t)(g * 300 + d0 + j) * 300 + d];
    }
    if (tid < 16) bsh[tid] = bhh[(tid >> 2) * 300 + d0 + (tid & 3)];
    if (tid < 32) lsh[tid] = lengths[tid];
    __syncthreads();

    float creg = 0.f;
    int bb = tid & 31, jj = (tid >> 5) & 3;
    volatile unsigned* barp = &g_bar;
    const float* W0 = Wsh + (rg + 0) * 300;
    const float* W1 = Wsh + (rg + 1) * 300;
    const float* W2 = Wsh + (rg + 2) * 300;
    const float* W3 = Wsh + (rg + 3) * 300;
    int dbeg = half * 150;

    for (int t = 0; t < Sv; ++t) {
        // prefetch XIT for this step (independent of h)
        float xi[4];
        if (tid < 128) {
#pragma unroll
            for (int g = 0; g < 4; g++)
                xi[g] = XIT[((size_t)t * G4 + g * 300 + d0 + jj) * 32 + bb];
        }

        const float* hin = g_hT[t & 1];
        float* hout = g_hT[(t + 1) & 1];
        for (int i = tid; i < 2400; i += 256)
            ((float4*)hTs)[i] = ((const float4*)hin)[i];
        __syncthreads();

        {
            float a0 = 0.f, a1 = 0.f, a2 = 0.f, a3 = 0.f;
#pragma unroll 5
            for (int dd = 0; dd < 150; dd += 2) {
                int d = dbeg + dd;
                float hv0 = hTs[d * 32 + lane];
                float hv1 = hTs[(d + 1) * 32 + lane];
                float2 w0 = *(const float2*)(W0 + d);
                float2 w1 = *(const float2*)(W1 + d);
                float2 w2 = *(const float2*)(W2 + d);
                float2 w3 = *(const float2*)(W3 + d);
                a0 += w0.x * hv0 + w0.y * hv1;
                a1 += w1.x * hv0 + w1.y * hv1;
                a2 += w2.x * hv0 + w2.y * hv1;
                a3 += w3.x * hv0 + w3.y * hv1;
            }
            psum[half * 512 + (rg + 0) * 32 + lane] = a0;
            psum[half * 512 + (rg + 1) * 32 + lane] = a1;
            psum[half * 512 + (rg + 2) * 32 + lane] = a2;
            psum[half * 512 + (rg + 3) * 32 + lane] = a3;
        }
        __syncthreads();

        if (tid < 128) {
            float gv[4];
#pragma unroll
            for (int g = 0; g < 4; g++) {
                int row = g * 4 + jj;
                gv[g] = xi[g] + bsh[row] + psum[row * 32 + bb] +
                        psum[512 + row * 32 + bb];
            }
            float hnew;
            if (t < lsh[bb]) {
                float gi = sigmoidf_(gv[0]);
                float gf = sigmoidf_(gv[1]);
                float gg = tanhf(gv[2]);
                float go = sigmoidf_(gv[3]);
                creg = gf * creg + gi * gg;
                hnew = go * tanhf(creg);
            } else {
                hnew = hTs[(d0 + jj) * 32 + bb];
            }
            hout[(d0 + jj) * 32 + bb] = hnew;
        }
        __threadfence();
        __syncthreads();
        if (tid == 0) {
            atomicAdd((unsigned*)&g_bar, 1u);
            unsigned target = (unsigned)(t + 1) * NC_LSTM;
            while (*barp < target) {
            }
            __threadfence();
        }
        __syncthreads();
    }
}

// ---------------- RNN readout -------------------------------------------------
__device__ __forceinline__ float warp_dot300(const float* __restrict__ wv,
                                             const float* hs, int lane) {
    float4 a0 = *(const float4*)(wv + lane * 4);
    float4 b0 = *(const float4*)(hs + lane * 4);
    float s = a0.x * b0.x + a0.y * b0.y + a0.z * b0.z + a0.w * b0.w;
    float4 a1 = *(const float4*)(wv + 128 + lane * 4);
    float4 b1 = *(const float4*)(hs + 128 + lane * 4);
    s += a1.x * b1.x + a1.y * b1.y + a1.z * b1.z + a1.w * b1.w;
    if (lane < 11) {
        float4 a2 = *(const float4*)(wv + 256 + lane * 4);
        float4 b2 = *(const float4*)(hs + 256 + lane * 4);
        s += a2.x * b2.x + a2.y * b2.y + a2.z * b2.z + a2.w * b2.w;
    }
#pragma unroll
    for (int off = 16; off > 0; off >>= 1)
        s += __shfl_down_sync(0xffffffffu, s, off);
    return s;
}

__global__ void k_rnn(const float* __restrict__ qT, const float* __restrict__ Wih,
                      const float* __restrict__ Whh, const float* __restrict__ bih,
                      const float* __restrict__ bhh, float* __restrict__ H) {
    int b = blockIdx.x;
    int tid = threadIdx.x;  // 320
    int warp = tid >> 5, lane = tid & 31;
    __shared__ __align__(16) float qs[Dv];
    __shared__ __align__(16) float hs[Dv];
    __shared__ float A[Dv];
    __shared__ float hn[Dv];
    for (int i = tid; i < Dv; i += 320) {
        qs[i] = qT[i * 32 + b];
        hs[i] = 0.f;
    }
    __syncthreads();
    for (int r = warp; r < Dv; r += 10) {
        float s = warp_dot300(Wih + (size_t)r * Dv, qs, lane);
        if (lane == 0) A[r] = s + bih[r] + bhh[r];
    }
    __syncthreads();
    for (int k = 0; k < Kv; k++) {
        for (int r = warp; r < Dv; r += 10) {
            float s = warp_dot300(Whh + (size_t)r * Dv, hs, lane);
            if (lane == 0) hn[r] = tanhf(A[r] + s);
        }
        __syncthreads();
        for (int i = tid; i < Dv; i += 320) {
            float v = hn[i];
            hs[i] = v;
            H[(size_t)b * Kv * Dv + k * Dv + i] = v;
        }
        __syncthreads();
    }
}

// ---------------- attention ---------------------------------------------------
__global__ void k_attn(const float* __restrict__ H, const float* __restrict__ V,
                       const int* __restrict__ lengths, float* __restrict__ R) {
    int kk = blockIdx.x, b = blockIdx.y;
    int tid = threadIdx.x;  // 128
    __shared__ __align__(16) float Hs[Dv];
    __shared__ float rbuf[128];
    __shared__ float p[128];
    for (int i = tid; i < Dv; i += 128)
        Hs[i] = H[(size_t)b * Kv * Dv + kk * Dv + i];
    __syncthreads();
    int len = lengths[b];
    float sc = -1e30f;
    if (tid < len) {
        const float* vrow = V + (size_t)(b * Sv + tid) * Dv;
        float s = 0.f;
        for (int d = 0; d < Dv; d += 4) {
            float4 v4 = *(const float4*)&vrow[d];
            s += v4.x * Hs[d] + v4.y * Hs[d + 1] + v4.z * Hs[d + 2] + v4.w * Hs[d + 3];
        }
        sc = s;
    }
    rbuf[tid] = sc;
    __syncthreads();
    for (int s = 64; s > 0; s >>= 1) {
        if (tid < s) rbuf[tid] = fmaxf(rbuf[tid], rbuf[tid + s]);
        __syncthreads();
    }
    float m = rbuf[0];
    __syncthreads();
    float e = (tid < len) ? __expf(sc - m) : 0.f;
    rbuf[tid] = e;
    __syncthreads();
    for (int s = 64; s > 0; s >>= 1) {
        if (tid < s) rbuf[tid] += rbuf[tid + s];
        __syncthreads();
    }
    float denom = rbuf[0];
    __syncthreads();
    p[tid] = e / denom;
    __syncthreads();
    float* out = R + (size_t)(b * Kv + kk) * Dv;
    for (int d = tid; d < Dv; d += 128) {
        float s = 0.f;
        for (int si = 0; si < Sv; si++)
            s += p[si] * V[(size_t)(b * Sv + si) * Dv + d];
        out[d] = s;
    }
}

// ---------------- launch ------------------------------------------------------
extern "C" void kernel_launch(void* const* d_in, const int* in_sizes, int n_in,
                              void* d_out, int out_size) {
    const float* words    = (const float*)d_in[0];
    const int*   lengths  = (const int*)d_in[1];
    const float* vocab    = (const float*)d_in[2];
    const float* dembed   = (const float*)d_in[3];
    const float* W        = (const float*)d_in[4];
    const float* lstm_Wih = (const float*)d_in[5];
    const float* lstm_Whh = (const float*)d_in[6];
    const float* lstm_bih = (const float*)d_in[7];
    const float* lstm_bhh = (const float*)d_in[8];
    const float* rnn_Wih  = (const float*)d_in[9];
    const float* rnn_Whh  = (const float*)d_in[10];
    const float* rnn_bih  = (const float*)d_in[11];
    const float* rnn_bhh  = (const float*)d_in[12];
    float* out = (float*)d_out;

    float *pE, *pRS, *pPL, *pV, *pVP, *pXIT, *pHT, *pH;
    unsigned *pwH, *pwL, *pWH, *pWL, *pXH, *pXL, *pCTH, *pCTL, *pEH, *pEL;
    unsigned *pvoH, *pvoL, *pVH, *pVL, *pWiH, *pWiL;
    cudaGetSymbolAddress((void**)&pE, g_E);
    cudaGetSymbolAddress((void**)&pRS, g_rowsum);
    cudaGetSymbolAddress((void**)&pPL, g_pl);
    cudaGetSymbolAddress((void**)&pV, g_V);
    cudaGetSymbolAddress((void**)&pVP, g_Vpart);
    cudaGetSymbolAddress((void**)&pXIT, g_XIT);
    cudaGetSymbolAddress((void**)&pHT, g_hT);
    cudaGetSymbolAddress((void**)&pH, g_H);
    cudaGetSymbolAddress((void**)&pwH, g_wordsH);
    cudaGetSymbolAddress((void**)&pwL, g_wordsL);
    cudaGetSymbolAddress((void**)&pWH, g_WH);
    cudaGetSymbolAddress((void**)&pWL, g_WL);
    cudaGetSymbolAddress((void**)&pXH, g_XH);
    cudaGetSymbolAddress((void**)&pXL, g_XL);
    cudaGetSymbolAddress((void**)&pCTH, g_CTH);
    cudaGetSymbolAddress((void**)&pCTL, g_CTL);
    cudaGetSymbolAddress((void**)&pEH, g_EH);
    cudaGetSymbolAddress((void**)&pEL, g_EL);
    cudaGetSymbolAddress((void**)&pvoH, g_vocH);
    cudaGetSymbolAddress((void**)&pvoL, g_vocL);
    cudaGetSymbolAddress((void**)&pVH, g_VH);
    cudaGetSymbolAddress((void**)&pVL, g_VL);
    cudaGetSymbolAddress((void**)&pWiH, g_WihTH);
    cudaGetSymbolAddress((void**)&pWiL, g_WihTL);

    cudaFuncSetAttribute(mma_nn, cudaFuncAttributeMaxDynamicSharedMemorySize,
                         MMA_SMEM);
    cudaFuncSetAttribute(k_lstm, cudaFuncAttributeMaxDynamicSharedMemorySize,
                         63488);

    // 0) inits + pre-split operands
    k_init0<<<RROWS / 256, 256>>>();
    k_splitA<<<(RROWS * 150 + 255) / 256, 256>>>(words, RROWS, Dv, pwH, pwL, 160);
    k_splitB_N<<<(150 * Dv + 255) / 256, 256>>>(W, Dv, Dv, pWH, pWL, 304);
    k_splitB_T<<<dim3((VOC + 1 + 31) / 32, 10), dim3(32, 8)>>>(
        vocab, VOC, Dv, dembed, pCTH, pCTL, ESTRIDE);
    k_splitB_N<<<(10000 * Dv + 255) / 256, 256>>>(vocab, VOC, Dv, pvoH, pvoL,
                                                  304);
    k_splitB_T<<<dim3((G4 + 31) / 32, 10), dim3(32, 8)>>>(
        lstm_Wih, G4, Dv, nullptr, pWiH, pWiL, 1204);

    // 1) X = words @ W  (epi 3: split packs)
    mma_nn<<<dim3(32, 3, 1), 512, MMA_SMEM>>>(
        pwH, pwL, 160, pWH, pWL, 304, nullptr, nullptr, 0, pXH, pXL, 160, Dv,
        150, 150, 0, 3);

    // 2) logits = X @ CT -> g_E fp32 + fused row-max (epi 5)
    mma_nn<<<dim3(32, 157, 1), 512, MMA_SMEM>>>(
        pXH, pXL, 160, pCTH, pCTL, ESTRIDE, nullptr, pE, ESTRIDE, nullptr,
        nullptr, 0, VOC + 1, 150, 150, 0, 5);

    // 3) single-pass softmax -> split exp packs + pl + rowsum
    k_softmax<<<RROWS, 256>>>(pE, pEH, pEL, pPL, pRS);

    // 4) V partials (split-K) then reduce + epilogue + split
    mma_nn<<<dim3(32, 3, SPLITK), 512, MMA_SMEM>>>(
        pEH, pEL, 10000, pvoH, pvoL, 304, nullptr, pVP, VPART_LD, nullptr,
        nullptr, 0, Dv, KSPL2, 10000, (size_t)RROWS * VPART_LD, 2);
    k_vreduce<<<(RROWS * 150 + 255) / 256, 256>>>(pVP, pPL, pRS, words, pV, pVH,
                                                  pVL);

    // 5) XI = V @ WihT + bih -> XIT (epi 4)
    mma_nn<<<dim3(32, 10, 1), 512, MMA_SMEM>>>(
        pVH, pVL, 160, pWiH, pWiL, 1204, lstm_bih, pXIT, 0, nullptr, nullptr, 0,
        G4, 150, 150, 0, 4);

    // 6) persistent LSTM
    k_init<<<(Dv * Bv + 255) / 256, 256>>>();
    k_lstm<<<NC_LSTM, 256, 63488>>>(pXIT, lstm_Whh, lstm_bhh, lengths);

    // 7) RNN readout
    k_rnn<<<Bv, 320>>>(pHT, rnn_Wih, rnn_Whh, rnn_bih, rnn_bhh, pH);

    // 8) attention -> output
    k_attn<<<dim3(Kv, Bv), 128>>>(pH, pV, lengths, out);
}

// round 7
// speedup vs baseline: 1.0191x; 1.0191x over previous
#include <cuda_runtime.h>
#include <cuda_bf16.h>
#include <math.h>

#define Bv 32
#define Sv 128
#define Dv 300
#define VOC 20000
#define Kv 8
#define RROWS 4096
#define G4 1200
#define ESTRIDE 20004
#define NC_LSTM 75
#define SPLITK 5
#define KSPL2 2000
#define VPART_LD 304

// ---------------- scratch (static device globals; zero-initialized) ----------
__device__ float g_E[(size_t)RROWS * ESTRIDE];
__device__ unsigned g_rowmax[RROWS];
__device__ float g_rowsum[RROWS];
__device__ float g_pl[RROWS];
__device__ float g_V[RROWS * Dv];
__device__ float g_Vpart[(size_t)SPLITK * RROWS * VPART_LD];
__device__ float g_XIT[(size_t)Sv * G4 * Bv];
__device__ float g_hT[2][Dv * Bv];
__device__ float g_H[Bv * Kv * Dv];
__device__ unsigned g_bar;

__device__ unsigned g_wordsH[RROWS * 160], g_wordsL[RROWS * 160];
__device__ unsigned g_WH[160 * 304], g_WL[160 * 304];
__device__ unsigned g_XH[RROWS * 160], g_XL[RROWS * 160];
__device__ unsigned g_CTH[(size_t)160 * ESTRIDE], g_CTL[(size_t)160 * ESTRIDE];
__device__ unsigned g_EH[(size_t)RROWS * 10000], g_EL[(size_t)RROWS * 10000];
__device__ unsigned g_vocH[10000 * 304], g_vocL[10000 * 304];
__device__ unsigned g_VH[RROWS * 160], g_VL[RROWS * 160];
__device__ unsigned g_WihTH[160 * 1204], g_WihTL[160 * 1204];

__device__ __forceinline__ float sigmoidf_(float x) {
    return 1.0f / (1.0f + __expf(-x));
}

// order-preserving float<->uint for atomicMax
__device__ __forceinline__ unsigned fenc(float f) {
    unsigned b = __float_as_uint(f);
    return (b & 0x80000000u) ? ~b : (b | 0x80000000u);
}
__device__ __forceinline__ float fdec(unsigned u) {
    return __uint_as_float((u & 0x80000000u) ? (u ^ 0x80000000u) : ~u);
}

__device__ __forceinline__ void split2(float x0, float x1, unsigned& hi,
                                       unsigned& lo) {
    __nv_bfloat16 h0 = __float2bfloat16_rn(x0);
    __nv_bfloat16 h1 = __float2bfloat16_rn(x1);
    float r0 = x0 - __bfloat162float(h0);
    float r1 = x1 - __bfloat162float(h1);
    __nv_bfloat16 l0 = __float2bfloat16_rn(r0);
    __nv_bfloat16 l1 = __float2bfloat16_rn(r1);
    hi = ((unsigned)__bfloat16_as_ushort(h1) << 16) | __bfloat16_as_ushort(h0);
    lo = ((unsigned)__bfloat16_as_ushort(l1) << 16) | __bfloat16_as_ushort(l0);
}

__device__ __forceinline__ void mma16(float* c, const unsigned* a,
                                      const unsigned* b) {
    asm volatile(
        "mma.sync.aligned.m16n8k16.row.col.f32.bf16.bf16.f32 "
        "{%0,%1,%2,%3}, {%4,%5,%6,%7}, {%8,%9}, {%0,%1,%2,%3};\n"
        : "+f"(c[0]), "+f"(c[1]), "+f"(c[2]), "+f"(c[3])
        : "r"(a[0]), "r"(a[1]), "r"(a[2]), "r"(a[3]), "r"(b[0]), "r"(b[1]));
}

__device__ __forceinline__ void cpa16(unsigned* dst, const unsigned* src,
                                      int bytes) {
    unsigned d = (unsigned)__cvta_generic_to_shared(dst);
    asm volatile("cp.async.cg.shared.global [%0], [%1], 16, %2;\n" ::"r"(d),
                 "l"(src), "r"(bytes));
}
__device__ __forceinline__ void cpa_commit() {
    asm volatile("cp.async.commit_group;\n");
}
__device__ __forceinline__ void cpa_wait1() {
    asm volatile("cp.async.wait_group 1;\n");
}

// ---------------- prepasses ---------------------------------------------------
__global__ void k_splitA(const float* __restrict__ src, int M, int K,
                         unsigned* __restrict__ hi, unsigned* __restrict__ lo,
                         int lda2) {
    int idx = blockIdx.x * 256 + threadIdx.x;
    int K2 = K >> 1;
    if (idx >= M * K2) return;
    int m = idx / K2, j = idx - m * K2;
    float2 v = *(const float2*)&src[(size_t)m * K + 2 * j];
    unsigned h, l;
    split2(v.x, v.y, h, l);
    hi[(size_t)m * lda2 + j] = h;
    lo[(size_t)m * lda2 + j] = l;
}

__global__ void k_splitB_N(const float* __restrict__ src, int K, int N,
                           unsigned* __restrict__ hi, unsigned* __restrict__ lo,
                           int ldo) {
    int idx = blockIdx.x * 256 + threadIdx.x;
    int K2 = K >> 1;
    if (idx >= K2 * N) return;
    int k2 = idx / N, n = idx - k2 * N;
    float a = src[(size_t)(2 * k2) * N + n];
    float b = src[(size_t)(2 * k2 + 1) * N + n];
    unsigned h, l;
    split2(a, b, h, l);
    hi[(size_t)k2 * ldo + n] = h;
    lo[(size_t)k2 * ldo + n] = l;
}

__global__ void k_splitB_T(const float* __restrict__ src, int Nsrc, int K,
                           const float* __restrict__ alt,
                           unsigned* __restrict__ hi, unsigned* __restrict__ lo,
                           int ldo) {
    __shared__ float tile[32][33];
    int n0 = blockIdx.x * 32, k0 = blockIdx.y * 32;
    int x = threadIdx.x, y = threadIdx.y;
    int Ntot = Nsrc + (alt ? 1 : 0);
    for (int i = y; i < 32; i += 8) {
        int n = n0 + i, k = k0 + x;
        float v = 0.f;
        if (k < K) {
            if (n < Nsrc) v = src[(size_t)n * K + k];
            else if (alt != nullptr && n == Nsrc) v = alt[k];
        }
        tile[i][x] = v;
    }
    __syncthreads();
    for (int i = y; i < 16; i += 8) {
        int k2 = (k0 >> 1) + i;
        int n = n0 + x;
        if (n < Ntot) {
            unsigned h, l;
            split2(tile[x][2 * i], tile[x][2 * i + 1], h, l);
            hi[(size_t)k2 * ldo + n] = h;
            lo[(size_t)k2 * ldo + n] = l;
        }
    }
}

// ---------------- split-bf16 NN GEMM, cp.async 3-stage, BN=160 ---------------
// BM=128, BN=160, BK=32 (16 k-pairs), 512 threads, 16 warps (4m x 4n),
// warp tile 32m x 40n (5 nj). Scalar LDS fragments (validated round-5 loop).
// epi 0: fp32 C (+bias). epi 2: fp32 partial. epi 3: split packs.
// epi 4: bias + XIT scatter. epi 5: fp32 C + fused row-max atomics.
#define APITCH 20
#define ABUFW 2560
#define BPITCH 164
#define BBUFW 2624
#define STGW 10368
#define MMA_SMEM (3 * STGW * 4)
#define NJ 5

__global__ __launch_bounds__(512) void mma_nn(
    const unsigned* __restrict__ Agh, const unsigned* __restrict__ Agl, int lda2,
    const unsigned* __restrict__ Bgh, const unsigned* __restrict__ Bgl, int ldb,
    const float* __restrict__ bias, float* __restrict__ C, int ldc,
    unsigned* __restrict__ Ch, unsigned* __restrict__ Cl, int ldc2,
    int N, int ksplit2, int K2, size_t partStride, int epi) {
    extern __shared__ unsigned smem[];
    int tid = threadIdx.x;
    int m0 = blockIdx.x * 128, n0 = blockIdx.y * 160;
    int kb2 = blockIdx.z * ksplit2;
    int ks2 = K2 - kb2;
    if (ks2 > ksplit2) ks2 = ksplit2;
    int nIter = (ks2 + 15) >> 4;

    int lane = tid & 31, w = tid >> 5;
    int wm = (w >> 2) * 32, wn = (w & 3) * 40;

    // A load mapping: 128 rows x 4 uint4-chunks (16 k2)
    int am = tid >> 2, ac = tid & 3;
    // B load mapping: 16 rows x 40 uint4-chunks = 640 chunks over 512 threads
    int bk0 = tid / 40, bc0 = tid % 40;
    int u1 = tid + 512;
    int bk1 = u1 / 40, bc1 = u1 % 40;
    int c00 = n0 + bc0 * 4;
    int v0 = N - c00;
    int by0 = v0 >= 4 ? 16 : (v0 > 0 ? v0 * 4 : 0);
    int cc0 = (by0 > 0) ? c00 : n0;
    int c01 = n0 + bc1 * 4;
    int v1 = N - c01;
    int by1 = v1 >= 4 ? 16 : (v1 > 0 ? v1 * 4 : 0);
    int cc1 = (by1 > 0) ? c01 : n0;
    bool has1 = (u1 < 640);

    float c[2][NJ][4];
#pragma unroll
    for (int i = 0; i < 2; i++)
#pragma unroll
        for (int j = 0; j < NJ; j++)
#pragma unroll
            for (int q = 0; q < 4; q++) c[i][j][q] = 0.f;

    // prologue: stages 0,1
#pragma unroll
    for (int p = 0; p < 2; p++) {
        if (p < nIter) {
            unsigned* sb = smem + p * STGW;
            size_t aidx = (size_t)(m0 + am) * lda2 + kb2 + (p << 4) + ac * 4;
            cpa16(&sb[am * APITCH + ac * 4], Agh + aidx, 16);
            cpa16(&sb[ABUFW + am * APITCH + ac * 4], Agl + aidx, 16);
            size_t b0 = (size_t)(kb2 + (p << 4) + bk0) * ldb + cc0;
            cpa16(&sb[2 * ABUFW + bk0 * BPITCH + bc0 * 4], Bgh + b0, by0);
            cpa16(&sb[2 * ABUFW + BBUFW + bk0 * BPITCH + bc0 * 4], Bgl + b0, by0);
            if (has1) {
                size_t b1 = (size_t)(kb2 + (p << 4) + bk1) * ldb + cc1;
                cpa16(&sb[2 * ABUFW + bk1 * BPITCH + bc1 * 4], Bgh + b1, by1);
                cpa16(&sb[2 * ABUFW + BBUFW + bk1 * BPITCH + bc1 * 4], Bgl + b1,
                      by1);
            }
        }
        cpa_commit();
    }

    for (int it = 0; it < nIter; ++it) {
        cpa_wait1();
        __syncthreads();

        // issue stage it+2
        if (it + 2 < nIter) {
            unsigned* sb2 = smem + ((it + 2) % 3) * STGW;
            int k2base = (it + 2) << 4;
            size_t aidx = (size_t)(m0 + am) * lda2 + kb2 + k2base + ac * 4;
            cpa16(&sb2[am * APITCH + ac * 4], Agh + aidx, 16);
            cpa16(&sb2[ABUFW + am * APITCH + ac * 4], Agl + aidx, 16);
            size_t b0 = (size_t)(kb2 + k2base + bk0) * ldb + cc0;
            cpa16(&sb2[2 * ABUFW + bk0 * BPITCH + bc0 * 4], Bgh + b0, by0);
            cpa16(&sb2[2 * ABUFW + BBUFW + bk0 * BPITCH + bc0 * 4], Bgl + b0,
                  by0);
            if (has1) {
                size_t b1 = (size_t)(kb2 + k2base + bk1) * ldb + cc1;
                cpa16(&sb2[2 * ABUFW + bk1 * BPITCH + bc1 * 4], Bgh + b1, by1);
                cpa16(&sb2[2 * ABUFW + BBUFW + bk1 * BPITCH + bc1 * 4], Bgl + b1,
                      by1);
            }
        }
        cpa_commit();

        const unsigned* sb = smem + (it % 3) * STGW;
        const unsigned* AhiB = sb;
        const unsigned* AloB = sb + ABUFW;
        const unsigned* BhiB = sb + 2 * ABUFW;
        const unsigned* BloB = sb + 2 * ABUFW + BBUFW;

#pragma unroll
        for (int s = 0; s < 2; s++) {
            int k2a = s * 8 + (lane & 3);
            unsigned ah[2][4], al[2][4];
#pragma unroll
            for (int mi = 0; mi < 2; mi++) {
                int r = wm + mi * 16 + (lane >> 2);
                ah[mi][0] = AhiB[r * APITCH + k2a];
                ah[mi][1] = AhiB[(r + 8) * APITCH + k2a];
                ah[mi][2] = AhiB[r * APITCH + k2a + 4];
                ah[mi][3] = AhiB[(r + 8) * APITCH + k2a + 4];
                al[mi][0] = AloB[r * APITCH + k2a];
                al[mi][1] = AloB[(r + 8) * APITCH + k2a];
                al[mi][2] = AloB[r * APITCH + k2a + 4];
                al[mi][3] = AloB[(r + 8) * APITCH + k2a + 4];
            }
#pragma unroll
            for (int nj = 0; nj < NJ; nj++) {
                int nb = wn + nj * 8 + (lane >> 2);
                unsigned bh[2], bl[2];
                bh[0] = BhiB[k2a * BPITCH + nb];
                bh[1] = BhiB[(k2a + 4) * BPITCH + nb];
                bl[0] = BloB[k2a * BPITCH + nb];
                bl[1] = BloB[(k2a + 4) * BPITCH + nb];
#pragma unroll
                for (int mi = 0; mi < 2; mi++) {
                    mma16(c[mi][nj], ah[mi], bh);
                    mma16(c[mi][nj], ah[mi], bl);
                    mma16(c[mi][nj], al[mi], bh);
                }
            }
        }
    }

    // ---- epilogue ----
#pragma unroll
    for (int mi = 0; mi < 2; mi++) {
        int r1 = m0 + wm + mi * 16 + (lane >> 2);
        int r2 = r1 + 8;
#pragma unroll
        for (int nj = 0; nj < NJ; nj++) {
            int col0 = n0 + wn + nj * 8 + (lane & 3) * 2;
            if (epi == 3) {
                if (col0 + 1 < N) {
                    unsigned h, l;
                    split2(c[mi][nj][0], c[mi][nj][1], h, l);
                    Ch[(size_t)r1 * ldc2 + (col0 >> 1)] = h;
                    Cl[(size_t)r1 * ldc2 + (col0 >> 1)] = l;
                    split2(c[mi][nj][2], c[mi][nj][3], h, l);
                    Ch[(size_t)r2 * ldc2 + (col0 >> 1)] = h;
                    Cl[(size_t)r2 * ldc2 + (col0 >> 1)] = l;
                }
            } else if (epi == 4) {
#pragma unroll
                for (int q = 0; q < 2; q++) {
                    int col = col0 + q;
                    if (col < N) {
                        float b = bias[col];
                        C[((size_t)(r1 & 127) * G4 + col) * 32 + (r1 >> 7)] =
                            c[mi][nj][q] + b;
                        C[((size_t)(r2 & 127) * G4 + col) * 32 + (r2 >> 7)] =
                            c[mi][nj][2 + q] + b;
                    }
                }
            } else {
                float* Cp = C + blockIdx.z * partStride;
#pragma unroll
                for (int q = 0; q < 2; q++) {
                    int col = col0 + q;
                    if (col < N) {
                        float v1 = c[mi][nj][q];
                        float v2 = c[mi][nj][2 + q];
                        if (epi == 0 && bias != nullptr) {
                            v1 += bias[col];
                            v2 += bias[col];
                        }
                        Cp[(size_t)r1 * ldc + col] = v1;
                        Cp[(size_t)r2 * ldc + col] = v2;
                    }
                }
            }
        }
    }

    if (epi == 5) {
#pragma unroll
        for (int mi = 0; mi < 2; mi++) {
            int r1 = m0 + wm + mi * 16 + (lane >> 2);
            float m1 = -1e30f, m2 = -1e30f;
#pragma unroll
            for (int nj = 0; nj < NJ; nj++) {
                int col0 = n0 + wn + nj * 8 + (lane & 3) * 2;
#pragma unroll
                for (int q = 0; q < 2; q++) {
                    if (col0 + q < N) {
                        m1 = fmaxf(m1, c[mi][nj][q]);
                        m2 = fmaxf(m2, c[mi][nj][2 + q]);
                    }
                }
            }
#pragma unroll
            for (int off = 1; off <= 2; off <<= 1) {
                m1 = fmaxf(m1, __shfl_xor_sync(0xffffffffu, m1, off));
                m2 = fmaxf(m2, __shfl_xor_sync(0xffffffffu, m2, off));
            }
            if ((lane & 3) == 0) {
                atomicMax(&g_rowmax[r1], fenc(m1));
                atomicMax(&g_rowmax[r1 + 8], fenc(m2));
            }
        }
    }
}

// ---------------- single-pass softmax (row max precomputed) ------------------
__global__ void k_softmax(const float* __restrict__ E, unsigned* __restrict__ EH,
                          unsigned* __restrict__ EL, float* __restrict__ pl,
                          float* __restrict__ rowsum) {
    int r = blockIdx.x;
    const float2* row2 = (const float2*)(E + (size_t)r * ESTRIDE);
    int tid = threadIdx.x;  // 256
    __shared__ float red[256];
    float m = fdec(g_rowmax[r]);
    float sum = 0.f;
    for (int j = tid; j < 10000; j += 256) {
        float2 f = row2[j];
        float e0 = __expf(f.x - m);
        float e1 = __expf(f.y - m);
        sum += e0 + e1;
        unsigned h, l;
        split2(e0, e1, h, l);
        EH[(size_t)r * 10000 + j] = h;
        EL[(size_t)r * 10000 + j] = l;
    }
    if (tid == 0) {
        float e = __expf(E[(size_t)r * ESTRIDE + VOC] - m);
        pl[r] = e;
        sum += e;
    }
    red[tid] = sum;
    __syncthreads();
    for (int s = 128; s > 0; s >>= 1) {
        if (tid < s) red[tid] += red[tid + s];
        __syncthreads();
    }
    if (tid == 0) rowsum[r] = red[0];
}

// ---------------- split-K reduce + V epilogue + V split ----------------------
__global__ void k_vreduce(const float* __restrict__ part,
                          const float* __restrict__ pl,
                          const float* __restrict__ rowsum,
                          const float* __restrict__ words,
                          float* __restrict__ V, unsigned* __restrict__ VH,
                          unsigned* __restrict__ VL) {
    int idx = blockIdx.x * 256 + threadIdx.x;
    if (idx >= RROWS * 150) return;
    int r = idx / 150, j = idx - r * 150;
    int d0 = 2 * j;
    float s0 = 0.f, s1 = 0.f;
#pragma unroll
    for (int z = 0; z < SPLITK; z++) {
        const float* p = part + (size_t)z * RROWS * VPART_LD +
                         (size_t)r * VPART_LD + d0;
        s0 += p[0];
        s1 += p[1];
    }
    float p_l = pl[r];
    float inv = 1.0f / rowsum[r];
    float v0 = (s0 + p_l * words[(size_t)r * Dv + d0]) * inv;
    float v1 = (s1 + p_l * words[(size_t)r * Dv + d0 + 1]) * inv;
    V[(size_t)r * Dv + d0] = v0;
    V[(size_t)r * Dv + d0 + 1] = v1;
    unsigned h, l;
    split2(v0, v1, h, l);
    VH[(size_t)r * 160 + j] = h;
    VL[(size_t)r * 160 + j] = l;
}

// ---------------- inits -------------------------------------------------------
__global__ void k_init0() {
    int i = blockIdx.x * blockDim.x + threadIdx.x;
    if (i < RROWS) g_rowmax[i] = 0u;
}
__global__ void k_init() {
    int i = blockIdx.x * blockDim.x + threadIdx.x;
    if (i < Dv * Bv) g_hT[0][i] = 0.f;
    if (i == 0) g_bar = 0u;
}

// ---------------- persistent LSTM (lane = batch) ------------------------------
__global__ __launch_bounds__(256) void k_lstm(const float* __restrict__ XIT,
                                              const float* __restrict__ Whh,
                                              const float* __restrict__ bhh,
                                              const int* __restrict__ lengths) {
    extern __shared__ float sm[];
    float* Wsh = sm;              // [16][300]
    float* hTs = Wsh + 4800;      // [300][32]
    float* psum = hTs + 9600;     // [2][16][32]
    float* bsh = psum + 1024;     // [16]
    int* lsh = (int*)(bsh + 16);  // [32]

    int tid = threadIdx.x, lane = tid & 31, w = tid >> 5;
    int d0 = blockIdx.x * 4;
    int half = w >> 2;
    int rg = (w & 3) * 4;

    for (int i = tid; i < 4800; i += 256) {
        int row = i / 300, d = i - row * 300;
        int g = row >> 2, j = row & 3;
        Wsh[i] = Whh[(size_t)(g * 300 + d0 + j) * 300 + d];
    }
    if (tid < 16) bsh[tid] = bhh[(tid >> 2) * 300 + d0 + (tid & 3)];
    if (tid < 32) lsh[tid] = lengths[tid];
    __syncthreads();

    float creg = 0.f;
    int bb = tid & 31, jj = (tid >> 5) & 3;
    volatile unsigned* barp = &g_bar;
    const float* W0 = Wsh + (rg + 0) * 300;
    const float* W1 = Wsh + (rg + 1) * 300;
    const float* W2 = Wsh + (rg + 2) * 300;
    const float* W3 = Wsh + (rg + 3) * 300;
    int dbeg = half * 150;

    for (int t = 0; t < Sv; ++t) {
        float xi[4];
        if (tid < 128) {
#pragma unroll
            for (int g = 0; g < 4; g++)
                xi[g] = XIT[((size_t)t * G4 + g * 300 + d0 + jj) * 32 + bb];
        }

        const float* hin = g_hT[t & 1];
        float* hout = g_hT[(t + 1) & 1];
        for (int i = tid; i < 2400; i += 256)
            ((float4*)hTs)[i] = ((const float4*)hin)[i];
        __syncthreads();

        {
            float a0 = 0.f, a1 = 0.f, a2 = 0.f, a3 = 0.f;
#pragma unroll 5
            for (int dd = 0; dd < 150; dd += 2) {
                int d = dbeg + dd;
                float hv0 = hTs[d * 32 + lane];
                float hv1 = hTs[(d + 1) * 32 + lane];
                float2 w0 = *(const float2*)(W0 + d);
                float2 w1 = *(const float2*)(W1 + d);
                float2 w2 = *(const float2*)(W2 + d);
                float2 w3 = *(const float2*)(W3 + d);
                a0 += w0.x * hv0 + w0.y * hv1;
                a1 += w1.x * hv0 + w1.y * hv1;
                a2 += w2.x * hv0 + w2.y * hv1;
                a3 += w3.x * hv0 + w3.y * hv1;
            }
            psum[half * 512 + (rg + 0) * 32 + lane] = a0;
            psum[half * 512 + (rg + 1) * 32 + lane] = a1;
            psum[half * 512 + (rg + 2) * 32 + lane] = a2;
            psum[half * 512 + (rg + 3) * 32 + lane] = a3;
        }
        __syncthreads();

        if (tid < 128) {
            float gv[4];
#pragma unroll
            for (int g = 0; g < 4; g++) {
                int row = g * 4 + jj;
                gv[g] = xi[g] + bsh[row] + psum[row * 32 + bb] +
                        psum[512 + row * 32 + bb];
            }
            float hnew;
            if (t < lsh[bb]) {
                float gi = sigmoidf_(gv[0]);
                float gf = sigmoidf_(gv[1]);
                float gg = tanhf(gv[2]);
                float go = sigmoidf_(gv[3]);
                creg = gf * creg + gi * gg;
                hnew = go * tanhf(creg);
            } else {
                hnew = hTs[(d0 + jj) * 32 + bb];
            }
            hout[(d0 + jj) * 32 + bb] = hnew;
        }
        __threadfence();
        __syncthreads();
        if (tid == 0) {
            atomicAdd((unsigned*)&g_bar, 1u);
            unsigned target = (unsigned)(t + 1) * NC_LSTM;
            while (*barp < target) {
            }
            __threadfence();
        }
        __syncthreads();
    }
}

// ---------------- RNN readout -------------------------------------------------
__device__ __forceinline__ float warp_dot300(const float* __restrict__ wv,
                                             const float* hs, int lane) {
    float4 a0 = *(const float4*)(wv + lane * 4);
    float4 b0 = *(const float4*)(hs + lane * 4);
    float s = a0.x * b0.x + a0.y * b0.y + a0.z * b0.z + a0.w * b0.w;
    float4 a1 = *(const float4*)(wv + 128 + lane * 4);
    float4 b1 = *(const float4*)(hs + 128 + lane * 4);
    s += a1.x * b1.x + a1.y * b1.y + a1.z * b1.z + a1.w * b1.w;
    if (lane < 11) {
        float4 a2 = *(const float4*)(wv + 256 + lane * 4);
        float4 b2 = *(const float4*)(hs + 256 + lane * 4);
        s += a2.x * b2.x + a2.y * b2.y + a2.z * b2.z + a2.w * b2.w;
    }
#pragma unroll
    for (int off = 16; off > 0; off >>= 1)
        s += __shfl_down_sync(0xffffffffu, s, off);
    return s;
}

__global__ void k_rnn(const float* __restrict__ qT, const float* __restrict__ Wih,
                      const float* __restrict__ Whh, const float* __restrict__ bih,
                      const float* __restrict__ bhh, float* __restrict__ H) {
    int b = blockIdx.x;
    int tid = threadIdx.x;  // 320
    int warp = tid >> 5, lane = tid & 31;
    __shared__ __align__(16) float qs[Dv];
    __shared__ __align__(16) float hs[Dv];
    __shared__ float A[Dv];
    __shared__ float hn[Dv];
    for (int i = tid; i < Dv; i += 320) {
        qs[i] = qT[i * 32 + b];
        hs[i] = 0.f;
    }
    __syncthreads();
    for (int r = warp; r < Dv; r += 10) {
        float s = warp_dot300(Wih + (size_t)r * Dv, qs, lane);
        if (lane == 0) A[r] = s + bih[r] + bhh[r];
    }
    __syncthreads();
    for (int k = 0; k < Kv; k++) {
        for (int r = warp; r < Dv; r += 10) {
            float s = warp_dot300(Whh + (size_t)r * Dv, hs, lane);
            if (lane == 0) hn[r] = tanhf(A[r] + s);
        }
        __syncthreads();
        for (int i = tid; i < Dv; i += 320) {
            float v = hn[i];
            hs[i] = v;
            H[(size_t)b * Kv * Dv + k * Dv + i] = v;
        }
        __syncthreads();
    }
}

// ---------------- attention ---------------------------------------------------
__global__ void k_attn(const float* __restrict__ H, const float* __restrict__ V,
                       const int* __restrict__ lengths, float* __restrict__ R) {
    int kk = blockIdx.x, b = blockIdx.y;
    int tid = threadIdx.x;  // 128
    __shared__ __align__(16) float Hs[Dv];
    __shared__ float rbuf[128];
    __shared__ float p[128];
    for (int i = tid; i < Dv; i += 128)
        Hs[i] = H[(size_t)b * Kv * Dv + kk * Dv + i];
    __syncthreads();
    int len = lengths[b];
    float sc = -1e30f;
    if (tid < len) {
        const float* vrow = V + (size_t)(b * Sv + tid) * Dv;
        float s = 0.f;
        for (int d = 0; d < Dv; d += 4) {
            float4 v4 = *(const float4*)&vrow[d];
            s += v4.x * Hs[d] + v4.y * Hs[d + 1] + v4.z * Hs[d + 2] + v4.w * Hs[d + 3];
        }
        sc = s;
    }
    rbuf[tid] = sc;
    __syncthreads();
    for (int s = 64; s > 0; s >>= 1) {
        if (tid < s) rbuf[tid] = fmaxf(rbuf[tid], rbuf[tid + s]);
        __syncthreads();
    }
    float m = rbuf[0];
    __syncthreads();
    float e = (tid < len) ? __expf(sc - m) : 0.f;
    rbuf[tid] = e;
    __syncthreads();
    for (int s = 64; s > 0; s >>= 1) {
        if (tid < s) rbuf[tid] += rbuf[tid + s];
        __syncthreads();
    }
    float denom = rbuf[0];
    __syncthreads();
    p[tid] = e / denom;
    __syncthreads();
    float* out = R + (size_t)(b * Kv + kk) * Dv;
    for (int d = tid; d < Dv; d += 128) {
        float s = 0.f;
        for (int si = 0; si < Sv; si++)
            s += p[si] * V[(size_t)(b * Sv + si) * Dv + d];
        out[d] = s;
    }
}

// ---------------- launch ------------------------------------------------------
extern "C" void kernel_launch(void* const* d_in, const int* in_sizes, int n_in,
                              void* d_out, int out_size) {
    const float* words    = (const float*)d_in[0];
    const int*   lengths  = (const int*)d_in[1];
    const float* vocab    = (const float*)d_in[2];
    const float* dembed   = (const float*)d_in[3];
    const float* W        = (const float*)d_in[4];
    const float* lstm_Wih = (const float*)d_in[5];
    const float* lstm_Whh = (const float*)d_in[6];
    const float* lstm_bih = (const float*)d_in[7];
    const float* lstm_bhh = (const float*)d_in[8];
    const float* rnn_Wih  = (const float*)d_in[9];
    const float* rnn_Whh  = (const float*)d_in[10];
    const float* rnn_bih  = (const float*)d_in[11];
    const float* rnn_bhh  = (const float*)d_in[12];
    float* out = (float*)d_out;

    float *pE, *pRS, *pPL, *pV, *pVP, *pXIT, *pHT, *pH;
    unsigned *pwH, *pwL, *pWH, *pWL, *pXH, *pXL, *pCTH, *pCTL, *pEH, *pEL;
    unsigned *pvoH, *pvoL, *pVH, *pVL, *pWiH, *pWiL;
    cudaGetSymbolAddress((void**)&pE, g_E);
    cudaGetSymbolAddress((void**)&pRS, g_rowsum);
    cudaGetSymbolAddress((void**)&pPL, g_pl);
    cudaGetSymbolAddress((void**)&pV, g_V);
    cudaGetSymbolAddress((void**)&pVP, g_Vpart);
    cudaGetSymbolAddress((void**)&pXIT, g_XIT);
    cudaGetSymbolAddress((void**)&pHT, g_hT);
    cudaGetSymbolAddress((void**)&pH, g_H);
    cudaGetSymbolAddress((void**)&pwH, g_wordsH);
    cudaGetSymbolAddress((void**)&pwL, g_wordsL);
    cudaGetSymbolAddress((void**)&pWH, g_WH);
    cudaGetSymbolAddress((void**)&pWL, g_WL);
    cudaGetSymbolAddress((void**)&pXH, g_XH);
    cudaGetSymbolAddress((void**)&pXL, g_XL);
    cudaGetSymbolAddress((void**)&pCTH, g_CTH);
    cudaGetSymbolAddress((void**)&pCTL, g_CTL);
    cudaGetSymbolAddress((void**)&pEH, g_EH);
    cudaGetSymbolAddress((void**)&pEL, g_EL);
    cudaGetSymbolAddress((void**)&pvoH, g_vocH);
    cudaGetSymbolAddress((void**)&pvoL, g_vocL);
    cudaGetSymbolAddress((void**)&pVH, g_VH);
    cudaGetSymbolAddress((void**)&pVL, g_VL);
    cudaGetSymbolAddress((void**)&pWiH, g_WihTH);
    cudaGetSymbolAddress((void**)&pWiL, g_WihTL);

    cudaFuncSetAttribute(mma_nn, cudaFuncAttributeMaxDynamicSharedMemorySize,
                         MMA_SMEM);
    cudaFuncSetAttribute(k_lstm, cudaFuncAttributeMaxDynamicSharedMemorySize,
                         63488);

    // 0) inits + pre-split operands
    k_init0<<<RROWS / 256, 256>>>();
    k_splitA<<<(RROWS * 150 + 255) / 256, 256>>>(words, RROWS, Dv, pwH, pwL, 160);
    k_splitB_N<<<(150 * Dv + 255) / 256, 256>>>(W, Dv, Dv, pWH, pWL, 304);
    k_splitB_T<<<dim3((VOC + 1 + 31) / 32, 10), dim3(32, 8)>>>(
        vocab, VOC, Dv, dembed, pCTH, pCTL, ESTRIDE);
    k_splitB_N<<<(10000 * Dv + 255) / 256, 256>>>(vocab, VOC, Dv, pvoH, pvoL,
                                                  304);
    k_splitB_T<<<dim3((G4 + 31) / 32, 10), dim3(32, 8)>>>(
        lstm_Wih, G4, Dv, nullptr, pWiH, pWiL, 1204);

    // 1) X = words @ W  (epi 3: split packs)
    mma_nn<<<dim3(32, 2, 1), 512, MMA_SMEM>>>(
        pwH, pwL, 160, pWH, pWL, 304, nullptr, nullptr, 0, pXH, pXL, 160, Dv,
        150, 150, 0, 3);

    // 2) logits = X @ CT -> g_E fp32 + fused row-max (epi 5)
    mma_nn<<<dim3(32, 126, 1), 512, MMA_SMEM>>>(
        pXH, pXL, 160, pCTH, pCTL, ESTRIDE, nullptr, pE, ESTRIDE, nullptr,
        nullptr, 0, VOC + 1, 150, 150, 0, 5);

    // 3) single-pass softmax -> split exp packs + pl + rowsum
    k_softmax<<<RROWS, 256>>>(pE, pEH, pEL, pPL, pRS);

    // 4) V partials (split-K, 2 n-blocks) then reduce + epilogue + split
    mma_nn<<<dim3(32, 2, SPLITK), 512, MMA_SMEM>>>(
        pEH, pEL, 10000, pvoH, pvoL, 304, nullptr, pVP, VPART_LD, nullptr,
        nullptr, 0, Dv, KSPL2, 10000, (size_t)RROWS * VPART_LD, 2);
    k_vreduce<<<(RROWS * 150 + 255) / 256, 256>>>(pVP, pPL, pRS, words, pV, pVH,
                                                  pVL);

    // 5) XI = V @ WihT + bih -> XIT (epi 4)
    mma_nn<<<dim3(32, 8, 1), 512, MMA_SMEM>>>(
        pVH, pVL, 160, pWiH, pWiL, 1204, lstm_bih, pXIT, 0, nullptr, nullptr, 0,
        G4, 150, 150, 0, 4);

    // 6) persistent LSTM
    k_init<<<(Dv * Bv + 255) / 256, 256>>>();
    k_lstm<<<NC_LSTM, 256, 63488>>>(pXIT, lstm_Whh, lstm_bhh, lengths);

    // 7) RNN readout
    k_rnn<<<Bv, 320>>>(pHT, rnn_Wih, rnn_Whh, rnn_bih, rnn_bhh, pH);

    // 8) attention -> output
    k_attn<<<dim3(Kv, Bv), 128>>>(pH, pV, lengths, out);
}